// round 1
// baseline (speedup 1.0000x reference)
#include <cuda_runtime.h>
#include <cstdint>

#define ULL unsigned long long

// ---------- packed f32x2 helpers (sm_100+ PTX) ----------
__device__ __forceinline__ void fma2(ULL& d, ULL a, ULL b) {
    asm("fma.rn.f32x2 %0, %1, %2, %0;" : "+l"(d) : "l"(a), "l"(b));
}
__device__ __forceinline__ ULL mul2(ULL a, ULL b) {
    ULL d; asm("mul.rn.f32x2 %0, %1, %2;" : "=l"(d) : "l"(a), "l"(b)); return d;
}
__device__ __forceinline__ ULL pk(float lo, float hi) {
    ULL d; asm("mov.b64 %0, {%1, %2};" : "=l"(d) : "f"(lo), "f"(hi)); return d;
}
__device__ __forceinline__ float2 upk(ULL v) {
    float2 r; asm("mov.b64 {%0, %1}, %2;" : "=f"(r.x), "=f"(r.y) : "l"(v)); return r;
}

// ---------- static scratch (no allocations allowed) ----------
__device__ float g_UP[4096 * 256];
__device__ float g_UH[4096 * 256];
__device__ float g_W1cP[256 * 358];
__device__ float g_W1cH[256 * 154];
__device__ float g_H1[4096 * 358];
__device__ float g_H2[4096 * 358];

// =====================================================================
// Stage 1: per-sample U = Ac^T (emb ⊙ mask) Bc   →  Uout[B, 256]
// Block = 128 threads = 4 warps = 4 samples.
// Warp w: handles samples {2*(w>>1), 2*(w>>1)+1} over d-half (w&1).
// Each thread owns a d-PAIR (2 consecutive d); V kept in f32x2 registers.
// Ac is staged in smem duplicated as {a,a} pairs → FFMA2 feeds with no packs.
// =====================================================================
template<int L>
__global__ __launch_bounds__(128)
void encoder_reduce(const float* __restrict__ emb, const float* __restrict__ mask,
                    const float* __restrict__ Ac,  const float* __restrict__ Bc,
                    float* __restrict__ Uout)
{
    extern __shared__ __align__(16) char smem[];
    ULL*   acdup = (ULL*)smem;                       // L*16 dup pairs
    float* maskv = (float*)(smem + (size_t)L * 16 * 8);  // 4*L
    // epilogue reuse of the same smem:
    float* Bcs = (float*)smem;                       // 2048 floats
    float* Vs  = (float*)(smem + 8192);              // 4 * 16 * 130 floats

    const int tid  = threadIdx.x;
    const int w    = tid >> 5;
    const int lane = tid & 31;
    const int b0   = blockIdx.x * 4;

    // ---- prep: stage duplicated Ac and masks ----
    for (int i = tid; i < L * 16; i += 128) {
        float a = Ac[i];
        acdup[i] = pk(a, a);
    }
    for (int i = tid; i < 4 * L; i += 128) {
        int s = i / L, l = i - s * L;
        maskv[i] = mask[(size_t)(b0 + s) * L + l];
    }
    __syncthreads();

    const int sA = (w >> 1) * 2;
    const int sB = sA + 1;
    const int p  = ((w & 1) << 5) + lane;            // d-pair index 0..63
    const ULL* xA = (const ULL*)(emb + (size_t)(b0 + sA) * L * 128) + p;
    const ULL* xB = (const ULL*)(emb + (size_t)(b0 + sB) * L * 128) + p;
    const float* mA = maskv + sA * L;
    const float* mB = maskv + sB * L;

    ULL V0[16], V1[16];
#pragma unroll
    for (int q = 0; q < 16; q++) { V0[q] = 0ull; V1[q] = 0ull; }

#pragma unroll 4
    for (int l = 0; l < L; l++) {
        ULL x0 = xA[l * 64];
        ULL x1 = xB[l * 64];
        float m0 = mA[l], m1 = mB[l];
        x0 = mul2(x0, pk(m0, m0));
        x1 = mul2(x1, pk(m1, m1));
        const ulonglong2* ap = (const ulonglong2*)(acdup + l * 16);
#pragma unroll
        for (int qq = 0; qq < 8; qq++) {
            ulonglong2 aa = ap[qq];
            fma2(V0[2 * qq],     aa.x, x0);
            fma2(V0[2 * qq + 1], aa.y, x0);
            fma2(V1[2 * qq],     aa.x, x1);
            fma2(V1[2 * qq + 1], aa.y, x1);
        }
    }
    __syncthreads();   // acdup/maskv dead; reuse smem

    // ---- stage V into smem (padded rows: 130) ----
#pragma unroll
    for (int q = 0; q < 16; q++) {
        float2 v0 = upk(V0[q]);
        float2 v1 = upk(V1[q]);
        *(float2*)(Vs + sA * 2080 + q * 130 + 2 * p) = v0;
        *(float2*)(Vs + sB * 2080 + q * 130 + 2 * p) = v1;
    }
    for (int i = tid; i < 2048; i += 128) Bcs[i] = Bc[i];
    __syncthreads();

    // ---- U = V @ Bc : one warp per sample ----
    {
        const int s  = w;
        const int q  = lane >> 1;
        const int r0 = (lane & 1) * 8;
        ULL u[4] = {0ull, 0ull, 0ull, 0ull};
        const float* vrow = Vs + s * 2080 + q * 130;
#pragma unroll 4
        for (int d = 0; d < 128; d++) {
            float v = vrow[d];
            ULL vv = pk(v, v);
            const ulonglong2* brow = (const ulonglong2*)(Bcs + d * 16 + r0);
            ulonglong2 b01 = brow[0];
            ulonglong2 b23 = brow[1];
            fma2(u[0], vv, b01.x);
            fma2(u[1], vv, b01.y);
            fma2(u[2], vv, b23.x);
            fma2(u[3], vv, b23.y);
        }
        ULL* dst = (ULL*)(Uout + (size_t)(b0 + s) * 256 + q * 16 + r0);
        dst[0] = u[0]; dst[1] = u[1]; dst[2] = u[2]; dst[3] = u[3];
    }
}

// =====================================================================
// Big GEMM: C[M,N] = A[M,K] @ B[K,N] + bias[N]   (row-major, ldc given)
// 128x64 tile, BK=16, 256 threads, per-thread 8m x 4n as 4 f32x2 m-pairs.
// B staged in smem as duplicated {b,b} pairs → FFMA2 with zero packs.
// =====================================================================
__global__ __launch_bounds__(256)
void gemm_big(const float* __restrict__ A, const float* __restrict__ B,
              const float* __restrict__ bias, float* __restrict__ C,
              int M, int N, int K, int ldc)
{
    __shared__ float As[16][130];   // transposed tile, pad keeps 8B alignment
    __shared__ ULL   Bs[16][64];    // duplicated pairs

    const int tid = threadIdx.x;
    const int tx  = tid & 15;       // n: 16 * 4
    const int ty  = tid >> 4;       // m: 16 * 8
    const int bm  = blockIdx.y * 128;
    const int bn  = blockIdx.x * 64;

    ULL c[4][4];
#pragma unroll
    for (int i = 0; i < 4; i++)
#pragma unroll
        for (int j = 0; j < 4; j++) c[i][j] = 0ull;

    const int la_k = tid & 15, la_m = tid >> 4;
    const int lb_n = tid & 63, lb_k = tid >> 6;

    for (int k0 = 0; k0 < K; k0 += 16) {
#pragma unroll
        for (int i = 0; i < 8; i++) {
            int m  = la_m + i * 16;
            int kg = k0 + la_k;
            float v = (kg < K) ? A[(size_t)(bm + m) * K + kg] : 0.f;
            As[la_k][m] = v;
        }
#pragma unroll
        for (int i = 0; i < 4; i++) {
            int k  = lb_k + i * 4;
            int kg = k0 + k;
            int ng = bn + lb_n;
            float v = (kg < K && ng < N) ? B[(size_t)kg * N + ng] : 0.f;
            Bs[k][lb_n] = pk(v, v);
        }
        __syncthreads();
#pragma unroll
        for (int kk = 0; kk < 16; kk++) {
            ULL a[4];
#pragma unroll
            for (int i = 0; i < 4; i++)
                a[i] = *(const ULL*)(&As[kk][ty * 8 + 2 * i]);
            ulonglong2 b01 = *(const ulonglong2*)(&Bs[kk][tx * 4]);
            ulonglong2 b23 = *(const ulonglong2*)(&Bs[kk][tx * 4 + 2]);
            ULL b[4] = {b01.x, b01.y, b23.x, b23.y};
#pragma unroll
            for (int i = 0; i < 4; i++)
#pragma unroll
                for (int j = 0; j < 4; j++)
                    fma2(c[i][j], a[i], b[j]);
        }
        __syncthreads();
    }

#pragma unroll
    for (int j = 0; j < 4; j++) {
        int n = bn + tx * 4 + j;
        if (n >= N) continue;
        float bv = bias[n];
#pragma unroll
        for (int i = 0; i < 4; i++) {
            float2 v = upk(c[i][j]);
            int m = bm + ty * 8 + 2 * i;
            C[(size_t)m * ldc + n]       = v.x + bv;
            C[(size_t)(m + 1) * ldc + n] = v.y + bv;
        }
    }
}

// =====================================================================
// Small GEMM (weight pre-combine W1c = Hc @ W1): M=256, tiny.
// =====================================================================
__global__ __launch_bounds__(256)
void gemm_small(const float* __restrict__ A, const float* __restrict__ B,
                float* __restrict__ C, int M, int N, int K)
{
    __shared__ float As[32][33];
    __shared__ float Bs[32][33];
    const int tid = threadIdx.x;
    const int tx = tid & 15, ty = tid >> 4;
    const int bm = blockIdx.y << 5, bn = blockIdx.x << 5;
    float c00 = 0, c01 = 0, c10 = 0, c11 = 0;

    for (int k0 = 0; k0 < K; k0 += 32) {
#pragma unroll
        for (int i = 0; i < 4; i++) {
            int idx = tid + (i << 8);
            int k = idx & 31, m = idx >> 5;
            int kg = k0 + k;
            As[k][m] = (kg < K && (bm + m) < M) ? A[(size_t)(bm + m) * K + kg] : 0.f;
            int kb = idx >> 5, nb = idx & 31;
            int kgb = k0 + kb, ng = bn + nb;
            Bs[kb][nb] = (kgb < K && ng < N) ? B[(size_t)kgb * N + ng] : 0.f;
        }
        __syncthreads();
#pragma unroll
        for (int kk = 0; kk < 32; kk++) {
            float a0 = As[kk][ty * 2], a1 = As[kk][ty * 2 + 1];
            float b0 = Bs[kk][tx * 2], b1 = Bs[kk][tx * 2 + 1];
            c00 += a0 * b0; c01 += a0 * b1;
            c10 += a1 * b0; c11 += a1 * b1;
        }
        __syncthreads();
    }
    int m0 = bm + ty * 2, n0 = bn + tx * 2;
    if (m0 < M) {
        if (n0 < N)     C[(size_t)m0 * N + n0]     = c00;
        if (n0 + 1 < N) C[(size_t)m0 * N + n0 + 1] = c01;
    }
    if (m0 + 1 < M) {
        if (n0 < N)     C[(size_t)(m0 + 1) * N + n0]     = c10;
        if (n0 + 1 < N) C[(size_t)(m0 + 1) * N + n0 + 1] = c11;
    }
}

// =====================================================================
// Rowwise LayerNorm (+affine) + ReLU.  One warp per row, values in regs.
// =====================================================================
__global__ __launch_bounds__(128)
void ln_relu(const float* __restrict__ H1, const float* __restrict__ g,
             const float* __restrict__ beta, float* __restrict__ H2, int N)
{
    const int w = threadIdx.x >> 5, lane = threadIdx.x & 31;
    const int row = blockIdx.x * 4 + w;
    const float* src = H1 + (size_t)row * N;
    float x[12];
    float s = 0.f, s2 = 0.f;
#pragma unroll
    for (int i = 0; i < 12; i++) {
        int idx = lane + 32 * i;
        float v = (idx < N) ? src[idx] : 0.f;
        x[i] = v; s += v; s2 += v * v;
    }
#pragma unroll
    for (int o = 16; o > 0; o >>= 1) {
        s  += __shfl_xor_sync(0xffffffffu, s, o);
        s2 += __shfl_xor_sync(0xffffffffu, s2, o);
    }
    float inv = 1.f / (float)N;
    float mu = s * inv;
    float var = s2 * inv - mu * mu;
    float rstd = rsqrtf(var + 1e-5f);
    float* dst = H2 + (size_t)row * N;
#pragma unroll
    for (int i = 0; i < 12; i++) {
        int idx = lane + 32 * i;
        if (idx < N) {
            float h = (x[i] - mu) * rstd * g[idx] + beta[idx];
            dst[idx] = fmaxf(h, 0.f);
        }
    }
}

// =====================================================================
// Host launcher
// =====================================================================
extern "C" void kernel_launch(void* const* d_in, const int* in_sizes, int n_in,
                              void* d_out, int out_size)
{
    const float* emb_P  = (const float*)d_in[0];
    const float* mask_P = (const float*)d_in[1];
    const float* emb_H  = (const float*)d_in[2];
    const float* mask_H = (const float*)d_in[3];
    const float* pep_Bc = (const float*)d_in[4];
    const float* pep_Ac = (const float*)d_in[5];
    const float* pep_Hc = (const float*)d_in[6];
    const float* pep_W1 = (const float*)d_in[7];
    const float* pep_b1 = (const float*)d_in[8];
    const float* pep_g  = (const float*)d_in[9];
    const float* pep_be = (const float*)d_in[10];
    const float* pep_W2 = (const float*)d_in[11];
    const float* pep_b2 = (const float*)d_in[12];
    const float* hla_Bc = (const float*)d_in[13];
    const float* hla_Ac = (const float*)d_in[14];
    const float* hla_Hc = (const float*)d_in[15];
    const float* hla_W1 = (const float*)d_in[16];
    const float* hla_b1 = (const float*)d_in[17];
    const float* hla_g  = (const float*)d_in[18];
    const float* hla_be = (const float*)d_in[19];
    const float* hla_W2 = (const float*)d_in[20];
    const float* hla_b2 = (const float*)d_in[21];
    float* out = (float*)d_out;

    float *UP, *UH, *W1cP, *W1cH, *H1, *H2;
    cudaGetSymbolAddress((void**)&UP,   g_UP);
    cudaGetSymbolAddress((void**)&UH,   g_UH);
    cudaGetSymbolAddress((void**)&W1cP, g_W1cP);
    cudaGetSymbolAddress((void**)&W1cH, g_W1cH);
    cudaGetSymbolAddress((void**)&H1,   g_H1);
    cudaGetSymbolAddress((void**)&H2,   g_H2);

    // dynamic smem: L=384 needs 55296B (AcDup 48K + masks 6K); epilogue 41472B
    const int smemH = 384 * 16 * 8 + 4 * 384 * 4;      // 55296
    const int smemP = 8192 + 4 * 2080 * 4;             // 41472 (epilogue dominates)
    cudaFuncSetAttribute(encoder_reduce<384>, cudaFuncAttributeMaxDynamicSharedMemorySize, smemH);
    cudaFuncSetAttribute(encoder_reduce<32>,  cudaFuncAttributeMaxDynamicSharedMemorySize, smemP);

    // ---- weight pre-combine: W1c = Hc @ W1 ----
    gemm_small<<<dim3(12, 8), 256>>>(pep_Hc, pep_W1, W1cP, 256, 358, 358);
    gemm_small<<<dim3(5, 8),  256>>>(hla_Hc, hla_W1, W1cH, 256, 154, 154);

    // ---- stage 1: encoder reductions ----
    encoder_reduce<32><<<1024, 128, smemP>>>(emb_P, mask_P, pep_Ac, pep_Bc, UP);
    encoder_reduce<384><<<1024, 128, smemH>>>(emb_H, mask_H, hla_Ac, hla_Bc, UH);

    // ---- pep branch ----
    gemm_big<<<dim3(6, 32), 256>>>(UP, W1cP, pep_b1, H1, 4096, 358, 256, 358);
    ln_relu<<<1024, 128>>>(H1, pep_g, pep_be, H2, 358);
    gemm_big<<<dim3(6, 32), 256>>>(H2, pep_W2, pep_b2, out, 4096, 358, 358, 512);

    // ---- hla branch ----
    gemm_big<<<dim3(3, 32), 256>>>(UH, W1cH, hla_b1, H1, 4096, 154, 256, 154);
    ln_relu<<<1024, 128>>>(H1, hla_g, hla_be, H2, 154);
    gemm_big<<<dim3(3, 32), 256>>>(H2, hla_W2, hla_b2, out + 358, 4096, 154, 154, 512);
}

// round 2
// speedup vs baseline: 1.4019x; 1.4019x over previous
#include <cuda_runtime.h>
#include <cstdint>

#define ULL unsigned long long

// ---------- packed f32x2 helpers (sm_100+ PTX) ----------
__device__ __forceinline__ void fma2(ULL& d, ULL a, ULL b) {
    asm("fma.rn.f32x2 %0, %1, %2, %0;" : "+l"(d) : "l"(a), "l"(b));
}
__device__ __forceinline__ ULL mul2(ULL a, ULL b) {
    ULL d; asm("mul.rn.f32x2 %0, %1, %2;" : "=l"(d) : "l"(a), "l"(b)); return d;
}
__device__ __forceinline__ ULL pk(float lo, float hi) {
    ULL d; asm("mov.b64 %0, {%1, %2};" : "=l"(d) : "f"(lo), "f"(hi)); return d;
}
__device__ __forceinline__ float2 upk(ULL v) {
    float2 r; asm("mov.b64 {%0, %1}, %2;" : "=f"(r.x), "=f"(r.y) : "l"(v)); return r;
}

// ---------- static scratch ----------
__device__ float g_UP[4096 * 256];
__device__ float g_UH[4096 * 256];
__device__ float g_W1cP[256 * 358];
__device__ float g_W1cH[256 * 154];
__device__ float g_H1P[4096 * 358];
__device__ float g_H1H[4096 * 154];
__device__ float g_H2P[4096 * 358];
__device__ float g_H2H[4096 * 154];

// =====================================================================
// Stage 1: per-sample U = Ac^T (emb ⊙ mask) Bc → Uout[B,256]
// Block = 128 thr = 4 warps = 2 samples. Warp w: sample w>>1, d-half w&1.
// Thread owns 2 consecutive d. Accumulators are q-PAIR packed f32x2
// (natural contiguous pairs of Ac rows → no duplication in smem),
// x is masked then duplicated in registers.
// =====================================================================
template<int L>
__global__ __launch_bounds__(128, 5)
void encoder2(const float* __restrict__ emb, const float* __restrict__ mask,
              const float* __restrict__ Ac,  const float* __restrict__ Bc,
              float* __restrict__ Uout)
{
    extern __shared__ __align__(16) char smem[];
    // phase 1
    float* acs  = (float*)smem;                  // L*16 raw Ac
    ULL*   mdup = (ULL*)(smem + (size_t)L * 64); // [2][L] dup masks
    // phase 2 (reuse after sync)
    float* Bcs = (float*)smem;                   // 2048
    float* Vs  = (float*)(smem + 8192);          // 2 * 16 * 130

    const int tid  = threadIdx.x;
    const int w    = tid >> 5;
    const int lane = tid & 31;
    const int b0   = blockIdx.x * 2;
    const int s    = w >> 1;    // sample within block
    const int h    = w & 1;     // d-half

    for (int i = tid; i < L * 16; i += 128) acs[i] = Ac[i];
    for (int i = tid; i < 2 * L; i += 128) {
        int ss = i / L, l = i - ss * L;
        float m = mask[(size_t)(b0 + ss) * L + l];
        mdup[i] = pk(m, m);
    }
    __syncthreads();

    const ULL* xg = (const ULL*)(emb + (size_t)(b0 + s) * L * 128) + h * 32 + lane;
    const ULL* mp = mdup + s * L;
    const ulonglong2* acp = (const ulonglong2*)acs;  // [L][4] pair-quads

    ULL V[16];
#pragma unroll
    for (int i = 0; i < 16; i++) V[i] = 0ull;

    for (int l0 = 0; l0 < L; l0 += 8) {
        ULL xb[8];
#pragma unroll
        for (int u = 0; u < 8; u++) xb[u] = xg[(size_t)(l0 + u) * 64];
#pragma unroll
        for (int u = 0; u < 8; u++) {
            const int l = l0 + u;
            ULL xm = mul2(xb[u], mp[l]);
            float2 f = upk(xm);
            ULL xl = pk(f.x, f.x);
            ULL xh = pk(f.y, f.y);
            ulonglong2 a01 = acp[l * 4 + 0];
            ulonglong2 a23 = acp[l * 4 + 1];
            ulonglong2 a45 = acp[l * 4 + 2];
            ulonglong2 a67 = acp[l * 4 + 3];
            fma2(V[0],  a01.x, xl);  fma2(V[1],  a01.x, xh);
            fma2(V[2],  a01.y, xl);  fma2(V[3],  a01.y, xh);
            fma2(V[4],  a23.x, xl);  fma2(V[5],  a23.x, xh);
            fma2(V[6],  a23.y, xl);  fma2(V[7],  a23.y, xh);
            fma2(V[8],  a45.x, xl);  fma2(V[9],  a45.x, xh);
            fma2(V[10], a45.y, xl);  fma2(V[11], a45.y, xh);
            fma2(V[12], a67.x, xl);  fma2(V[13], a67.y, xl);
            fma2(V[14], a67.x, xh);  fma2(V[15], a67.y, xh);
        }
    }
    __syncthreads();   // acs/mdup dead

    // stage V: Vs[s][q][d], pitch 130
    const int d0 = h * 64 + lane * 2;
    {
        float* vb = Vs + s * 2080;
#pragma unroll
        for (int qq = 0; qq < 8; qq++) {
            // V[2qq+dd] holds {q=2qq, q=2qq+1} for d = d0+dd  (note qq==6,7 order fixed below)
            ULL vlo, vhi;
            if (qq < 6)      { vlo = V[2 * qq]; vhi = V[2 * qq + 1]; }
            else if (qq == 6){ vlo = V[12];     vhi = V[14]; }
            else             { vlo = V[13];     vhi = V[15]; }
            float2 v0 = upk(vlo);   // d0
            float2 v1 = upk(vhi);   // d0+1
            vb[(2 * qq)     * 130 + d0]     = v0.x;
            vb[(2 * qq + 1) * 130 + d0]     = v0.y;
            vb[(2 * qq)     * 130 + d0 + 1] = v1.x;
            vb[(2 * qq + 1) * 130 + d0 + 1] = v1.y;
        }
    }
    for (int i = tid; i < 2048; i += 128) Bcs[i] = Bc[i];
    __syncthreads();

    // U = V @ Bc : warp computes 8 q-rows x 16 r for its sample
    {
        const int q  = h * 8 + (lane >> 2);
        const int r0 = (lane & 3) * 4;
        ULL u0 = 0ull, u1 = 0ull;
        const float* vrow = Vs + s * 2080 + q * 130;
#pragma unroll 8
        for (int d = 0; d < 128; d++) {
            float v = vrow[d];
            ULL vv = pk(v, v);
            ulonglong2 b2 = *(const ulonglong2*)(Bcs + d * 16 + r0);
            fma2(u0, vv, b2.x);
            fma2(u1, vv, b2.y);
        }
        ULL* dst = (ULL*)(Uout + (size_t)(b0 + s) * 256 + q * 16 + r0);
        dst[0] = u0; dst[1] = u1;
    }
}

// =====================================================================
// Fused dual-branch GEMM: C = A@B + bias. 128x64 tile, BK=32, 256 thr.
// blockIdx.z selects branch; blocks past N exit.
// =====================================================================
struct GemmArgs {
    const float* A; const float* B; const float* bias; float* C;
    int N, K, ldc;
};

__global__ __launch_bounds__(256)
void gemm_fused(GemmArgs g0, GemmArgs g1)
{
    const GemmArgs g = (blockIdx.z == 0) ? g0 : g1;
    const int bn = blockIdx.x * 64;
    if (bn >= g.N) return;
    const int bm = blockIdx.y * 128;

    __shared__ float As[32][132];
    __shared__ ULL   Bs[32][64];

    const int tid = threadIdx.x;
    const int tx  = tid & 15;
    const int ty  = tid >> 4;

    ULL c[4][4];
#pragma unroll
    for (int i = 0; i < 4; i++)
#pragma unroll
        for (int j = 0; j < 4; j++) c[i][j] = 0ull;

    const int a_k = (tid & 15) * 2;  // 0..30
    const int a_m = tid >> 4;        // 0..15
    const int b_n = tid & 63;
    const int b_k = tid >> 6;        // 0..3

    for (int k0 = 0; k0 < g.K; k0 += 32) {
#pragma unroll
        for (int i = 0; i < 8; i++) {
            int m  = a_m + i * 16;
            int kg = k0 + a_k;
            float2 v = make_float2(0.f, 0.f);
            if (kg + 1 < g.K) v = *(const float2*)(g.A + (size_t)(bm + m) * g.K + kg);
            else if (kg < g.K) v.x = g.A[(size_t)(bm + m) * g.K + kg];
            As[a_k][m]     = v.x;
            As[a_k + 1][m] = v.y;
        }
#pragma unroll
        for (int i = 0; i < 8; i++) {
            int k  = b_k + i * 4;
            int kg = k0 + k;
            int ng = bn + b_n;
            float v = (kg < g.K && ng < g.N) ? g.B[(size_t)kg * g.N + ng] : 0.f;
            Bs[k][b_n] = pk(v, v);
        }
        __syncthreads();
#pragma unroll
        for (int kk = 0; kk < 32; kk++) {
            ULL a[4];
#pragma unroll
            for (int i = 0; i < 4; i++)
                a[i] = *(const ULL*)(&As[kk][ty * 8 + 2 * i]);
            ulonglong2 b01 = *(const ulonglong2*)(&Bs[kk][tx * 4]);
            ulonglong2 b23 = *(const ulonglong2*)(&Bs[kk][tx * 4 + 2]);
            ULL b[4] = {b01.x, b01.y, b23.x, b23.y};
#pragma unroll
            for (int i = 0; i < 4; i++)
#pragma unroll
                for (int j = 0; j < 4; j++)
                    fma2(c[i][j], a[i], b[j]);
        }
        __syncthreads();
    }

#pragma unroll
    for (int j = 0; j < 4; j++) {
        int n = bn + tx * 4 + j;
        if (n >= g.N) continue;
        float bv = g.bias[n];
#pragma unroll
        for (int i = 0; i < 4; i++) {
            float2 v = upk(c[i][j]);
            int m = bm + ty * 8 + 2 * i;
            g.C[(size_t)m * g.ldc + n]       = v.x + bv;
            g.C[(size_t)(m + 1) * g.ldc + n] = v.y + bv;
        }
    }
}

// =====================================================================
// Small GEMM (weight pre-combine W1c = Hc @ W1)
// =====================================================================
__global__ __launch_bounds__(256)
void gemm_small(const float* __restrict__ A, const float* __restrict__ B,
                float* __restrict__ C, int M, int N, int K)
{
    __shared__ float As[32][33];
    __shared__ float Bs[32][33];
    const int tid = threadIdx.x;
    const int tx = tid & 15, ty = tid >> 4;
    const int bm = blockIdx.y << 5, bn = blockIdx.x << 5;
    float c00 = 0, c01 = 0, c10 = 0, c11 = 0;

    for (int k0 = 0; k0 < K; k0 += 32) {
#pragma unroll
        for (int i = 0; i < 4; i++) {
            int idx = tid + (i << 8);
            int k = idx & 31, m = idx >> 5;
            int kg = k0 + k;
            As[k][m] = (kg < K && (bm + m) < M) ? A[(size_t)(bm + m) * K + kg] : 0.f;
            int kb = idx >> 5, nb = idx & 31;
            int kgb = k0 + kb, ng = bn + nb;
            Bs[kb][nb] = (kgb < K && ng < N) ? B[(size_t)kgb * N + ng] : 0.f;
        }
        __syncthreads();
#pragma unroll
        for (int kk = 0; kk < 32; kk++) {
            float a0 = As[kk][ty * 2], a1 = As[kk][ty * 2 + 1];
            float b0 = Bs[kk][tx * 2], b1 = Bs[kk][tx * 2 + 1];
            c00 += a0 * b0; c01 += a0 * b1;
            c10 += a1 * b0; c11 += a1 * b1;
        }
        __syncthreads();
    }
    int m0 = bm + ty * 2, n0 = bn + tx * 2;
    if (m0 < M) {
        if (n0 < N)     C[(size_t)m0 * N + n0]     = c00;
        if (n0 + 1 < N) C[(size_t)m0 * N + n0 + 1] = c01;
    }
    if (m0 + 1 < M) {
        if (n0 < N)     C[(size_t)(m0 + 1) * N + n0]     = c10;
        if (n0 + 1 < N) C[(size_t)(m0 + 1) * N + n0 + 1] = c11;
    }
}

// =====================================================================
// Fused dual-branch LayerNorm + ReLU. One warp per row.
// =====================================================================
struct LnArgs { const float* H1; const float* g; const float* beta; float* H2; int N; };

__global__ __launch_bounds__(128)
void ln_fused(LnArgs a0, LnArgs a1)
{
    const LnArgs a = (blockIdx.z == 0) ? a0 : a1;
    const int w = threadIdx.x >> 5, lane = threadIdx.x & 31;
    const int row = blockIdx.x * 4 + w;
    const float* src = a.H1 + (size_t)row * a.N;
    float x[12];
    float s = 0.f, s2 = 0.f;
#pragma unroll
    for (int i = 0; i < 12; i++) {
        int idx = lane + 32 * i;
        float v = (idx < a.N) ? src[idx] : 0.f;
        x[i] = v; s += v; s2 += v * v;
    }
#pragma unroll
    for (int o = 16; o > 0; o >>= 1) {
        s  += __shfl_xor_sync(0xffffffffu, s, o);
        s2 += __shfl_xor_sync(0xffffffffu, s2, o);
    }
    float inv = 1.f / (float)a.N;
    float mu = s * inv;
    float var = s2 * inv - mu * mu;
    float rstd = rsqrtf(var + 1e-5f);
    float* dst = a.H2 + (size_t)row * a.N;
#pragma unroll
    for (int i = 0; i < 12; i++) {
        int idx = lane + 32 * i;
        if (idx < a.N) {
            float h = (x[i] - mu) * rstd * a.g[idx] + a.beta[idx];
            dst[idx] = fmaxf(h, 0.f);
        }
    }
}

// =====================================================================
// Host launcher
// =====================================================================
extern "C" void kernel_launch(void* const* d_in, const int* in_sizes, int n_in,
                              void* d_out, int out_size)
{
    const float* emb_P  = (const float*)d_in[0];
    const float* mask_P = (const float*)d_in[1];
    const float* emb_H  = (const float*)d_in[2];
    const float* mask_H = (const float*)d_in[3];
    const float* pep_Bc = (const float*)d_in[4];
    const float* pep_Ac = (const float*)d_in[5];
    const float* pep_Hc = (const float*)d_in[6];
    const float* pep_W1 = (const float*)d_in[7];
    const float* pep_b1 = (const float*)d_in[8];
    const float* pep_g  = (const float*)d_in[9];
    const float* pep_be = (const float*)d_in[10];
    const float* pep_W2 = (const float*)d_in[11];
    const float* pep_b2 = (const float*)d_in[12];
    const float* hla_Bc = (const float*)d_in[13];
    const float* hla_Ac = (const float*)d_in[14];
    const float* hla_Hc = (const float*)d_in[15];
    const float* hla_W1 = (const float*)d_in[16];
    const float* hla_b1 = (const float*)d_in[17];
    const float* hla_g  = (const float*)d_in[18];
    const float* hla_be = (const float*)d_in[19];
    const float* hla_W2 = (const float*)d_in[20];
    const float* hla_b2 = (const float*)d_in[21];
    float* out = (float*)d_out;

    float *UP, *UH, *W1cP, *W1cH, *H1P, *H1H, *H2P, *H2H;
    cudaGetSymbolAddress((void**)&UP,   g_UP);
    cudaGetSymbolAddress((void**)&UH,   g_UH);
    cudaGetSymbolAddress((void**)&W1cP, g_W1cP);
    cudaGetSymbolAddress((void**)&W1cH, g_W1cH);
    cudaGetSymbolAddress((void**)&H1P,  g_H1P);
    cudaGetSymbolAddress((void**)&H1H,  g_H1H);
    cudaGetSymbolAddress((void**)&H2P,  g_H2P);
    cudaGetSymbolAddress((void**)&H2H,  g_H2H);

    // dyn smem: phase1 = L*64 + 2L*8 ; phase2 = 8192 + 16640 = 24832
    const int smemH = 384 * 64 + 2 * 384 * 8;   // 30720 (> 24832)
    const int smemP = 24832;                     // phase2 dominates for L=32
    cudaFuncSetAttribute(encoder2<384>, cudaFuncAttributeMaxDynamicSharedMemorySize, smemH);
    cudaFuncSetAttribute(encoder2<32>,  cudaFuncAttributeMaxDynamicSharedMemorySize, smemP);

    // weight pre-combine: W1c = Hc @ W1
    gemm_small<<<dim3(12, 8), 256>>>(pep_Hc, pep_W1, W1cP, 256, 358, 358);
    gemm_small<<<dim3(5, 8),  256>>>(hla_Hc, hla_W1, W1cH, 256, 154, 154);

    // stage 1: encoder reductions (2 samples / block)
    encoder2<32><<<2048, 128, smemP>>>(emb_P, mask_P, pep_Ac, pep_Bc, UP);
    encoder2<384><<<2048, 128, smemH>>>(emb_H, mask_H, hla_Ac, hla_Bc, UH);

    // GEMM1 (both branches): H1 = U @ W1c + b1
    {
        GemmArgs gp { UP, W1cP, pep_b1, H1P, 358, 256, 358 };
        GemmArgs gh { UH, W1cH, hla_b1, H1H, 154, 256, 154 };
        gemm_fused<<<dim3(6, 32, 2), 256>>>(gp, gh);
    }

    // LN + ReLU (both branches)
    {
        LnArgs lp { H1P, pep_g, pep_be, H2P, 358 };
        LnArgs lh { H1H, hla_g, hla_be, H2H, 154 };
        ln_fused<<<dim3(1024, 1, 2), 128>>>(lp, lh);
    }

    // GEMM2 (both branches): out = H2 @ W2 + b2  (concat via column offset)
    {
        GemmArgs gp { H2P, pep_W2, pep_b2, out,       358, 358, 512 };
        GemmArgs gh { H2H, hla_W2, hla_b2, out + 358, 154, 154, 512 };
        gemm_fused<<<dim3(6, 32, 2), 256>>>(gp, gh);
    }
}

// round 3
// speedup vs baseline: 1.7558x; 1.2524x over previous
#include <cuda_runtime.h>
#include <cstdint>

#define ULL unsigned long long

// ---------- packed f32x2 helpers (sm_100+ PTX) ----------
__device__ __forceinline__ void fma2(ULL& d, ULL a, ULL b) {
    asm("fma.rn.f32x2 %0, %1, %2, %0;" : "+l"(d) : "l"(a), "l"(b));
}
__device__ __forceinline__ ULL mul2(ULL a, ULL b) {
    ULL d; asm("mul.rn.f32x2 %0, %1, %2;" : "=l"(d) : "l"(a), "l"(b)); return d;
}
__device__ __forceinline__ ULL pk(float lo, float hi) {
    ULL d; asm("mov.b64 %0, {%1, %2};" : "=l"(d) : "f"(lo), "f"(hi)); return d;
}
__device__ __forceinline__ float2 upk(ULL v) {
    float2 r; asm("mov.b64 {%0, %1}, %2;" : "=f"(r.x), "=f"(r.y) : "l"(v)); return r;
}

// ---------- static scratch ----------
__device__ float g_UP[4096 * 256];
__device__ float g_UH[4096 * 256];
__device__ float g_W1cP[256 * 358];
__device__ float g_W1cH[256 * 154];
__device__ float g_H1P[4096 * 358];
__device__ float g_H1H[4096 * 154];
__device__ float2 g_stP[4096];
__device__ float2 g_stH[4096];

struct EncArgs { const float* emb; const float* mask; const float* Ac; const float* Bc; float* U; int L; };
struct PreArgs { const float* A; const float* B; float* C; int N, K, nbx, nblocks; };
struct GemmArgs { const float* A; const float* B; const float* bias; float* C; int N, K, ldc; };

// =====================================================================
// Encoder device path: per-sample U = Ac^T (emb ⊙ mask) Bc
// Block = 128 thr = 4 warps = 4 samples (warp = sample).
// Thread owns 4 consecutive d (one LDG.128 per row l).
// Accumulators: 8 q-pairs x 4 d = 32 f32x2.
// =====================================================================
__device__ __forceinline__ void encoder_path(const EncArgs& e, char* smem)
{
    const int L = e.L;
    float* acs   = (float*)smem;                       // L*16 raw Ac
    float* maskS = (float*)(smem + (size_t)L * 64);    // 4*L masks
    // phase-2 overlay
    float* Bcs = (float*)smem;                         // 2048 floats
    float* Vs  = (float*)(smem + 8192);                // 4 * 8 * 132 floats

    const int tid  = threadIdx.x;
    const int s    = tid >> 5;       // warp = sample
    const int lane = tid & 31;
    const int b0   = blockIdx.x * 4;

    for (int i = tid; i < L * 16; i += 128) acs[i] = e.Ac[i];
    for (int i = tid; i < 4 * L; i += 128) {
        int ss = i / L, l = i - ss * L;
        maskS[i] = e.mask[(size_t)(b0 + ss) * L + l];
    }
    __syncthreads();

    const ulonglong2* xg = (const ulonglong2*)(e.emb + (size_t)(b0 + s) * L * 128) + lane;
    const float* msk = maskS + s * L;
    const ulonglong2* acp = (const ulonglong2*)acs;    // [L][4]

    ULL V[8][4];
#pragma unroll
    for (int p = 0; p < 8; p++)
#pragma unroll
        for (int j = 0; j < 4; j++) V[p][j] = 0ull;

    for (int l0 = 0; l0 < L; l0 += 2) {
        ulonglong2 xva = xg[(size_t)l0 * 32];
        ulonglong2 xvb = xg[(size_t)(l0 + 1) * 32];
#pragma unroll
        for (int u = 0; u < 2; u++) {
            const int l = l0 + u;
            ulonglong2 xv = u ? xvb : xva;
            float m = msk[l];
            ULL mm = pk(m, m);
            ULL x0 = mul2(xv.x, mm);
            ULL x1 = mul2(xv.y, mm);
            float2 fa = upk(x0), fb = upk(x1);
            ULL X[4];
            X[0] = pk(fa.x, fa.x); X[1] = pk(fa.y, fa.y);
            X[2] = pk(fb.x, fb.x); X[3] = pk(fb.y, fb.y);
            ulonglong2 a01 = acp[l * 4 + 0];
            ulonglong2 a23 = acp[l * 4 + 1];
            ulonglong2 a45 = acp[l * 4 + 2];
            ulonglong2 a67 = acp[l * 4 + 3];
            ULL a[8] = {a01.x, a01.y, a23.x, a23.y, a45.x, a45.y, a67.x, a67.y};
#pragma unroll
            for (int p = 0; p < 8; p++)
#pragma unroll
                for (int j = 0; j < 4; j++)
                    fma2(V[p][j], a[p], X[j]);
        }
    }
    __syncthreads();   // acs/maskS dead

    // load Bc once (overlay region)
    for (int i = tid; i < 2048; i += 128) Bcs[i] = e.Bc[i];

    const int d0 = lane * 4;
    const int qloc = lane >> 2;
    const int r0 = (lane & 3) * 4;
    float* vb = Vs + s * 8 * 132;

#pragma unroll
    for (int h = 0; h < 2; h++) {
        // stage this q-half of V
#pragma unroll
        for (int pp = 0; pp < 4; pp++) {
            int p = h * 4 + pp;
#pragma unroll
            for (int j = 0; j < 4; j++) {
                float2 v = upk(V[p][j]);
                int rq = 2 * pp;
                vb[rq * 132 + d0 + j]       = v.x;
                vb[(rq + 1) * 132 + d0 + j] = v.y;
            }
        }
        __syncthreads();

        // U(q-half) = V @ Bc
        ULL u0 = 0ull, u1 = 0ull;
        const float* vrow = vb + qloc * 132;
#pragma unroll 8
        for (int d = 0; d < 128; d++) {
            float v = vrow[d];
            ULL vv = pk(v, v);
            ulonglong2 b2 = *(const ulonglong2*)(Bcs + d * 16 + r0);
            fma2(u0, vv, b2.x);
            fma2(u1, vv, b2.y);
        }
        int q = h * 8 + qloc;
        ULL* dst = (ULL*)(e.U + (size_t)(b0 + s) * 256 + q * 16 + r0);
        dst[0] = u0; dst[1] = u1;
        __syncthreads();
    }
}

// =====================================================================
// Weight precombine path (W1c = Hc @ W1), 128 threads, 32x32 tiles
// =====================================================================
__device__ __forceinline__ void precombine_path(const PreArgs& p, char* smem)
{
    if ((int)blockIdx.x >= p.nblocks) return;
    float* As = (float*)smem;            // [32][33]
    float* Bs = As + 32 * 33;            // [32][33]
    const int tid = threadIdx.x;
    const int tx = tid & 15, ty = tid >> 4;      // n0 = tx*2, m0 = ty*4
    const int bn = (blockIdx.x % p.nbx) * 32;
    const int bm = (blockIdx.x / p.nbx) * 32;
    const int M = 256;

    float c[4][2];
#pragma unroll
    for (int i = 0; i < 4; i++) { c[i][0] = 0.f; c[i][1] = 0.f; }

    for (int k0 = 0; k0 < p.K; k0 += 32) {
#pragma unroll
        for (int i = 0; i < 8; i++) {
            int idx = tid + i * 128;
            int m = idx >> 5, k = idx & 31;
            int kg = k0 + k;
            As[k * 33 + m] = (kg < p.K && (bm + m) < M) ? p.A[(size_t)(bm + m) * p.K + kg] : 0.f;
            int kb = idx >> 5, nb = idx & 31;
            int kgb = k0 + kb, ng = bn + nb;
            Bs[kb * 33 + nb] = (kgb < p.K && ng < p.N) ? p.B[(size_t)kgb * p.N + ng] : 0.f;
        }
        __syncthreads();
#pragma unroll
        for (int kk = 0; kk < 32; kk++) {
            float b0 = Bs[kk * 33 + tx * 2], b1 = Bs[kk * 33 + tx * 2 + 1];
#pragma unroll
            for (int i = 0; i < 4; i++) {
                float a = As[kk * 33 + ty * 4 + i];
                c[i][0] += a * b0;
                c[i][1] += a * b1;
            }
        }
        __syncthreads();
    }
#pragma unroll
    for (int i = 0; i < 4; i++) {
        int m = bm + ty * 4 + i, n = bn + tx * 2;
        if (m < M) {
            if (n < p.N)     p.C[(size_t)m * p.N + n]     = c[i][0];
            if (n + 1 < p.N) p.C[(size_t)m * p.N + n + 1] = c[i][1];
        }
    }
}

// =====================================================================
// Fused prep launch: z=0/1 encoders, z=2/3 weight precombine
// =====================================================================
__global__ __launch_bounds__(128, 4)
void prep_fused(EncArgs e0, EncArgs e1, PreArgs p0, PreArgs p1)
{
    extern __shared__ __align__(16) char smem[];
    int z = blockIdx.z;
    if (z == 0)      encoder_path(e0, smem);
    else if (z == 1) encoder_path(e1, smem);
    else if (z == 2) precombine_path(p0, smem);
    else             precombine_path(p1, smem);
}

// =====================================================================
// GEMM1: C = A@B + bias (128x64 tile, BK=32, reg-prefetched)
// =====================================================================
__global__ __launch_bounds__(256)
void gemm_plain(GemmArgs g0, GemmArgs g1)
{
    const GemmArgs g = blockIdx.z ? g1 : g0;
    const int bn = blockIdx.x * 64;
    if (bn >= g.N) return;
    const int bm = blockIdx.y * 128;

    __shared__ float As[32][132];
    __shared__ ULL   Bs[32][64];

    const int tid = threadIdx.x;
    const int tx  = tid & 15;
    const int ty  = tid >> 4;
    const int a_k = (tid & 15) * 2;
    const int a_m = tid >> 4;
    const int b_n = tid & 63;
    const int b_k = tid >> 6;

    float2 pa[8]; float pb[8];

    auto fetch = [&](int k0) {
        int kg = k0 + a_k;
#pragma unroll
        for (int i = 0; i < 8; i++) {
            int m = bm + a_m + i * 16;
            float2 v = make_float2(0.f, 0.f);
            if (kg + 1 < g.K)      v = *(const float2*)(g.A + (size_t)m * g.K + kg);
            else if (kg < g.K)     v.x = g.A[(size_t)m * g.K + kg];
            pa[i] = v;
        }
#pragma unroll
        for (int i = 0; i < 8; i++) {
            int kgb = k0 + b_k + i * 4;
            int ng = bn + b_n;
            pb[i] = (kgb < g.K && ng < g.N) ? g.B[(size_t)kgb * g.N + ng] : 0.f;
        }
    };

    ULL c[4][4];
#pragma unroll
    for (int i = 0; i < 4; i++)
#pragma unroll
        for (int j = 0; j < 4; j++) c[i][j] = 0ull;

    fetch(0);
    for (int k0 = 0; k0 < g.K; k0 += 32) {
#pragma unroll
        for (int i = 0; i < 8; i++) {
            As[a_k][a_m + i * 16]     = pa[i].x;
            As[a_k + 1][a_m + i * 16] = pa[i].y;
        }
#pragma unroll
        for (int i = 0; i < 8; i++) Bs[b_k + i * 4][b_n] = pk(pb[i], pb[i]);
        __syncthreads();
        if (k0 + 32 < g.K) fetch(k0 + 32);
#pragma unroll
        for (int kk = 0; kk < 32; kk++) {
            ulonglong2 a01 = *(const ulonglong2*)&As[kk][ty * 8];
            ulonglong2 a23 = *(const ulonglong2*)&As[kk][ty * 8 + 4];
            ULL a[4] = {a01.x, a01.y, a23.x, a23.y};
            ulonglong2 b01 = *(const ulonglong2*)&Bs[kk][tx * 4];
            ulonglong2 b23 = *(const ulonglong2*)&Bs[kk][tx * 4 + 2];
            ULL b[4] = {b01.x, b01.y, b23.x, b23.y};
#pragma unroll
            for (int i = 0; i < 4; i++)
#pragma unroll
                for (int j = 0; j < 4; j++)
                    fma2(c[i][j], a[i], b[j]);
        }
        __syncthreads();
    }

#pragma unroll
    for (int j = 0; j < 4; j++) {
        int n = bn + tx * 4 + j;
        if (n >= g.N) continue;
        float bv = g.bias[n];
#pragma unroll
        for (int i = 0; i < 4; i++) {
            float2 v = upk(c[i][j]);
            int m = bm + ty * 8 + 2 * i;
            g.C[(size_t)m * g.ldc + n]       = v.x + bv;
            g.C[(size_t)(m + 1) * g.ldc + n] = v.y + bv;
        }
    }
}

// =====================================================================
// Row stats (mu, rstd) for LayerNorm — one warp per row
// =====================================================================
__global__ __launch_bounds__(128)
void stats_fused(const float* __restrict__ H1P, const float* __restrict__ H1H,
                 float2* __restrict__ stP, float2* __restrict__ stH, int NP, int NH)
{
    const float* H1 = blockIdx.z ? H1H : H1P;
    float2* st = blockIdx.z ? stH : stP;
    const int N = blockIdx.z ? NH : NP;
    const int w = threadIdx.x >> 5, lane = threadIdx.x & 31;
    const int row = blockIdx.x * 4 + w;
    const float* src = H1 + (size_t)row * N;
    float s = 0.f, s2 = 0.f;
#pragma unroll
    for (int i = 0; i < 12; i++) {
        int idx = lane + 32 * i;
        float v = (idx < N) ? src[idx] : 0.f;
        s += v; s2 += v * v;
    }
#pragma unroll
    for (int o = 16; o > 0; o >>= 1) {
        s  += __shfl_xor_sync(0xffffffffu, s, o);
        s2 += __shfl_xor_sync(0xffffffffu, s2, o);
    }
    if (lane == 0) {
        float inv = 1.f / (float)N;
        float mu = s * inv;
        float var = s2 * inv - mu * mu;
        st[row] = make_float2(mu, rsqrtf(var + 1e-5f));
    }
}

// =====================================================================
// GEMM2 with fused LN+ReLU on the A operand:
// C = relu((A - mu)*rstd*gam + bet) @ B + bias
// =====================================================================
__global__ __launch_bounds__(256)
void gemm_lnA(GemmArgs g0, GemmArgs g1,
              const float2* __restrict__ st0, const float2* __restrict__ st1,
              const float* __restrict__ gm0, const float* __restrict__ bt0,
              const float* __restrict__ gm1, const float* __restrict__ bt1)
{
    const GemmArgs g = blockIdx.z ? g1 : g0;
    const float2* stats = blockIdx.z ? st1 : st0;
    const float* gam = blockIdx.z ? gm1 : gm0;
    const float* bet = blockIdx.z ? bt1 : bt0;
    const int bn = blockIdx.x * 64;
    if (bn >= g.N) return;
    const int bm = blockIdx.y * 128;

    __shared__ float As[32][132];
    __shared__ ULL   Bs[32][64];

    const int tid = threadIdx.x;
    const int tx  = tid & 15;
    const int ty  = tid >> 4;
    const int a_k = (tid & 15) * 2;
    const int a_m = tid >> 4;
    const int b_n = tid & 63;
    const int b_k = tid >> 6;

    float2 st[8];
#pragma unroll
    for (int i = 0; i < 8; i++) st[i] = stats[bm + a_m + i * 16];

    float2 pa[8]; float pb[8];

    auto fetch = [&](int k0) {
        int kg = k0 + a_k;
        float2 gk = make_float2(0.f, 0.f), bb = make_float2(0.f, 0.f);
        bool ok0 = (kg < g.K), ok1 = (kg + 1 < g.K);
        if (ok1) { gk = *(const float2*)(gam + kg); bb = *(const float2*)(bet + kg); }
        else if (ok0) { gk.x = gam[kg]; bb.x = bet[kg]; }
#pragma unroll
        for (int i = 0; i < 8; i++) {
            int m = bm + a_m + i * 16;
            float2 v = make_float2(0.f, 0.f);
            if (ok1)      v = *(const float2*)(g.A + (size_t)m * g.K + kg);
            else if (ok0) v.x = g.A[(size_t)m * g.K + kg];
            float2 r = make_float2(0.f, 0.f);
            if (ok0) r.x = fmaxf(0.f, (v.x - st[i].x) * st[i].y * gk.x + bb.x);
            if (ok1) r.y = fmaxf(0.f, (v.y - st[i].x) * st[i].y * gk.y + bb.y);
            pa[i] = r;
        }
#pragma unroll
        for (int i = 0; i < 8; i++) {
            int kgb = k0 + b_k + i * 4;
            int ng = bn + b_n;
            pb[i] = (kgb < g.K && ng < g.N) ? g.B[(size_t)kgb * g.N + ng] : 0.f;
        }
    };

    ULL c[4][4];
#pragma unroll
    for (int i = 0; i < 4; i++)
#pragma unroll
        for (int j = 0; j < 4; j++) c[i][j] = 0ull;

    fetch(0);
    for (int k0 = 0; k0 < g.K; k0 += 32) {
#pragma unroll
        for (int i = 0; i < 8; i++) {
            As[a_k][a_m + i * 16]     = pa[i].x;
            As[a_k + 1][a_m + i * 16] = pa[i].y;
        }
#pragma unroll
        for (int i = 0; i < 8; i++) Bs[b_k + i * 4][b_n] = pk(pb[i], pb[i]);
        __syncthreads();
        if (k0 + 32 < g.K) fetch(k0 + 32);
#pragma unroll
        for (int kk = 0; kk < 32; kk++) {
            ulonglong2 a01 = *(const ulonglong2*)&As[kk][ty * 8];
            ulonglong2 a23 = *(const ulonglong2*)&As[kk][ty * 8 + 4];
            ULL a[4] = {a01.x, a01.y, a23.x, a23.y};
            ulonglong2 b01 = *(const ulonglong2*)&Bs[kk][tx * 4];
            ulonglong2 b23 = *(const ulonglong2*)&Bs[kk][tx * 4 + 2];
            ULL b[4] = {b01.x, b01.y, b23.x, b23.y};
#pragma unroll
            for (int i = 0; i < 4; i++)
#pragma unroll
                for (int j = 0; j < 4; j++)
                    fma2(c[i][j], a[i], b[j]);
        }
        __syncthreads();
    }

#pragma unroll
    for (int j = 0; j < 4; j++) {
        int n = bn + tx * 4 + j;
        if (n >= g.N) continue;
        float bv = g.bias[n];
#pragma unroll
        for (int i = 0; i < 4; i++) {
            float2 v = upk(c[i][j]);
            int m = bm + ty * 8 + 2 * i;
            g.C[(size_t)m * g.ldc + n]       = v.x + bv;
            g.C[(size_t)(m + 1) * g.ldc + n] = v.y + bv;
        }
    }
}

// =====================================================================
// Host launcher
// =====================================================================
extern "C" void kernel_launch(void* const* d_in, const int* in_sizes, int n_in,
                              void* d_out, int out_size)
{
    const float* emb_P  = (const float*)d_in[0];
    const float* mask_P = (const float*)d_in[1];
    const float* emb_H  = (const float*)d_in[2];
    const float* mask_H = (const float*)d_in[3];
    const float* pep_Bc = (const float*)d_in[4];
    const float* pep_Ac = (const float*)d_in[5];
    const float* pep_Hc = (const float*)d_in[6];
    const float* pep_W1 = (const float*)d_in[7];
    const float* pep_b1 = (const float*)d_in[8];
    const float* pep_g  = (const float*)d_in[9];
    const float* pep_be = (const float*)d_in[10];
    const float* pep_W2 = (const float*)d_in[11];
    const float* pep_b2 = (const float*)d_in[12];
    const float* hla_Bc = (const float*)d_in[13];
    const float* hla_Ac = (const float*)d_in[14];
    const float* hla_Hc = (const float*)d_in[15];
    const float* hla_W1 = (const float*)d_in[16];
    const float* hla_b1 = (const float*)d_in[17];
    const float* hla_g  = (const float*)d_in[18];
    const float* hla_be = (const float*)d_in[19];
    const float* hla_W2 = (const float*)d_in[20];
    const float* hla_b2 = (const float*)d_in[21];
    float* out = (float*)d_out;

    float *UP, *UH, *W1cP, *W1cH, *H1P, *H1H;
    float2 *stP, *stH;
    cudaGetSymbolAddress((void**)&UP,   g_UP);
    cudaGetSymbolAddress((void**)&UH,   g_UH);
    cudaGetSymbolAddress((void**)&W1cP, g_W1cP);
    cudaGetSymbolAddress((void**)&W1cH, g_W1cH);
    cudaGetSymbolAddress((void**)&H1P,  g_H1P);
    cudaGetSymbolAddress((void**)&H1H,  g_H1H);
    cudaGetSymbolAddress((void**)&stP,  g_stP);
    cudaGetSymbolAddress((void**)&stH,  g_stH);

    // dyn smem: max(L*64 + 4L*4, 8192 + 16896) ; L=384 -> 30720
    const int smemPrep = 384 * 64 + 4 * 384 * 4;   // 30720
    cudaFuncSetAttribute(prep_fused, cudaFuncAttributeMaxDynamicSharedMemorySize, smemPrep);

    // one launch: both encoders + both weight precombines
    {
        EncArgs eP { emb_P, mask_P, pep_Ac, pep_Bc, UP, 32 };
        EncArgs eH { emb_H, mask_H, hla_Ac, hla_Bc, UH, 384 };
        PreArgs pP { pep_Hc, pep_W1, W1cP, 358, 358, 12, 96 };
        PreArgs pH { hla_Hc, hla_W1, W1cH, 154, 154, 5, 40 };
        prep_fused<<<dim3(1024, 1, 4), 128, smemPrep>>>(eP, eH, pP, pH);
    }

    // GEMM1: H1 = U @ W1c + b1
    {
        GemmArgs gp { UP, W1cP, pep_b1, H1P, 358, 256, 358 };
        GemmArgs gh { UH, W1cH, hla_b1, H1H, 154, 256, 154 };
        gemm_plain<<<dim3(6, 32, 2), 256>>>(gp, gh);
    }

    // LN stats
    stats_fused<<<dim3(1024, 1, 2), 128>>>(H1P, H1H, stP, stH, 358, 154);

    // GEMM2 with fused LN+ReLU on A: out = relu(LN(H1)) @ W2 + b2
    {
        GemmArgs gp { H1P, pep_W2, pep_b2, out,       358, 358, 512 };
        GemmArgs gh { H1H, hla_W2, hla_b2, out + 358, 154, 154, 512 };
        gemm_lnA<<<dim3(6, 32, 2), 256>>>(gp, gh, stP, stH,
                                          pep_g, pep_be, hla_g, hla_be);
    }
}

// round 4
// speedup vs baseline: 1.9706x; 1.1224x over previous
#include <cuda_runtime.h>
#include <cstdint>

#define ULL unsigned long long

// ---------- packed f32x2 helpers (sm_100+ PTX) ----------
__device__ __forceinline__ void fma2(ULL& d, ULL a, ULL b) {
    asm("fma.rn.f32x2 %0, %1, %2, %0;" : "+l"(d) : "l"(a), "l"(b));
}
__device__ __forceinline__ ULL mul2(ULL a, ULL b) {
    ULL d; asm("mul.rn.f32x2 %0, %1, %2;" : "=l"(d) : "l"(a), "l"(b)); return d;
}
__device__ __forceinline__ ULL pk(float lo, float hi) {
    ULL d; asm("mov.b64 %0, {%1, %2};" : "=l"(d) : "f"(lo), "f"(hi)); return d;
}
__device__ __forceinline__ float2 upk(ULL v) {
    float2 r; asm("mov.b64 {%0, %1}, %2;" : "=f"(r.x), "=f"(r.y) : "l"(v)); return r;
}

// ---------- static scratch ----------
__device__ float g_UP[4096 * 256];
__device__ float g_UH[4096 * 256];
__device__ float g_W1cP[256 * 358];
__device__ float g_W1cH[256 * 154];
__device__ float g_H1P[4096 * 358];
__device__ float g_H1H[4096 * 154];

struct EncArgs { const float* emb; const float* mask; const float* Ac; const float* Bc; float* U; int L; };
struct PreArgs { const float* A; const float* B; float* C; int N, K, nbx, nblocks; };
struct GemmArgs { const float* A; const float* B; const float* bias; float* C; int N, K, ldc; };

// =====================================================================
// Encoder device path: per-sample U = Ac^T (emb ⊙ mask) Bc
// Block = 128 thr = 4 warps = 4 samples (warp = sample).
// Thread owns 4 consecutive d (one LDG.128 per row l).
// =====================================================================
__device__ __forceinline__ void encoder_path(const EncArgs& e, char* smem)
{
    const int L = e.L;
    float* acs   = (float*)smem;                       // L*16 raw Ac
    float* maskS = (float*)(smem + (size_t)L * 64);    // 4*L masks
    // phase-2 overlay
    float* Bcs = (float*)smem;                         // 2048 floats
    float* Vs  = (float*)(smem + 8192);                // 4 * 8 * 132 floats

    const int tid  = threadIdx.x;
    const int s    = tid >> 5;       // warp = sample
    const int lane = tid & 31;
    const int b0   = blockIdx.x * 4;

    for (int i = tid; i < L * 16; i += 128) acs[i] = e.Ac[i];
    for (int i = tid; i < 4 * L; i += 128) {
        int ss = i / L, l = i - ss * L;
        maskS[i] = e.mask[(size_t)(b0 + ss) * L + l];
    }
    __syncthreads();

    const ulonglong2* xg = (const ulonglong2*)(e.emb + (size_t)(b0 + s) * L * 128) + lane;
    const float* msk = maskS + s * L;
    const ulonglong2* acp = (const ulonglong2*)acs;    // [L][4]

    ULL V[8][4];
#pragma unroll
    for (int p = 0; p < 8; p++)
#pragma unroll
        for (int j = 0; j < 4; j++) V[p][j] = 0ull;

    for (int l0 = 0; l0 < L; l0 += 2) {
        ulonglong2 xva = xg[(size_t)l0 * 32];
        ulonglong2 xvb = xg[(size_t)(l0 + 1) * 32];
#pragma unroll
        for (int u = 0; u < 2; u++) {
            const int l = l0 + u;
            ulonglong2 xv = u ? xvb : xva;
            float m = msk[l];
            ULL mm = pk(m, m);
            ULL x0 = mul2(xv.x, mm);
            ULL x1 = mul2(xv.y, mm);
            float2 fa = upk(x0), fb = upk(x1);
            ULL X[4];
            X[0] = pk(fa.x, fa.x); X[1] = pk(fa.y, fa.y);
            X[2] = pk(fb.x, fb.x); X[3] = pk(fb.y, fb.y);
            ulonglong2 a01 = acp[l * 4 + 0];
            ulonglong2 a23 = acp[l * 4 + 1];
            ulonglong2 a45 = acp[l * 4 + 2];
            ulonglong2 a67 = acp[l * 4 + 3];
            ULL a[8] = {a01.x, a01.y, a23.x, a23.y, a45.x, a45.y, a67.x, a67.y};
#pragma unroll
            for (int p = 0; p < 8; p++)
#pragma unroll
                for (int j = 0; j < 4; j++)
                    fma2(V[p][j], a[p], X[j]);
        }
    }
    __syncthreads();   // acs/maskS dead

    for (int i = tid; i < 2048; i += 128) Bcs[i] = e.Bc[i];

    const int d0 = lane * 4;
    const int qloc = lane >> 2;
    const int r0 = (lane & 3) * 4;
    float* vb = Vs + s * 8 * 132;

#pragma unroll
    for (int h = 0; h < 2; h++) {
#pragma unroll
        for (int pp = 0; pp < 4; pp++) {
            int p = h * 4 + pp;
#pragma unroll
            for (int j = 0; j < 4; j++) {
                float2 v = upk(V[p][j]);
                int rq = 2 * pp;
                vb[rq * 132 + d0 + j]       = v.x;
                vb[(rq + 1) * 132 + d0 + j] = v.y;
            }
        }
        __syncthreads();

        ULL u0 = 0ull, u1 = 0ull;
        const float* vrow = vb + qloc * 132;
#pragma unroll 8
        for (int d = 0; d < 128; d++) {
            float v = vrow[d];
            ULL vv = pk(v, v);
            ulonglong2 b2 = *(const ulonglong2*)(Bcs + d * 16 + r0);
            fma2(u0, vv, b2.x);
            fma2(u1, vv, b2.y);
        }
        int q = h * 8 + qloc;
        ULL* dst = (ULL*)(e.U + (size_t)(b0 + s) * 256 + q * 16 + r0);
        dst[0] = u0; dst[1] = u1;
        __syncthreads();
    }
}

// =====================================================================
// Weight precombine path (W1c = Hc @ W1), 128 threads, 32x32 tiles
// =====================================================================
__device__ __forceinline__ void precombine_path(const PreArgs& p, char* smem)
{
    if ((int)blockIdx.x >= p.nblocks) return;
    float* As = (float*)smem;            // [32][33]
    float* Bs = As + 32 * 33;            // [32][33]
    const int tid = threadIdx.x;
    const int tx = tid & 15, ty = tid >> 4;
    const int bn = (blockIdx.x % p.nbx) * 32;
    const int bm = (blockIdx.x / p.nbx) * 32;
    const int M = 256;

    float c[4][2];
#pragma unroll
    for (int i = 0; i < 4; i++) { c[i][0] = 0.f; c[i][1] = 0.f; }

    for (int k0 = 0; k0 < p.K; k0 += 32) {
#pragma unroll
        for (int i = 0; i < 8; i++) {
            int idx = tid + i * 128;
            int m = idx >> 5, k = idx & 31;
            int kg = k0 + k;
            As[k * 33 + m] = (kg < p.K && (bm + m) < M) ? p.A[(size_t)(bm + m) * p.K + kg] : 0.f;
            int kb = idx >> 5, nb = idx & 31;
            int kgb = k0 + kb, ng = bn + nb;
            Bs[kb * 33 + nb] = (kgb < p.K && ng < p.N) ? p.B[(size_t)kgb * p.N + ng] : 0.f;
        }
        __syncthreads();
#pragma unroll
        for (int kk = 0; kk < 32; kk++) {
            float b0 = Bs[kk * 33 + tx * 2], b1 = Bs[kk * 33 + tx * 2 + 1];
#pragma unroll
            for (int i = 0; i < 4; i++) {
                float a = As[kk * 33 + ty * 4 + i];
                c[i][0] += a * b0;
                c[i][1] += a * b1;
            }
        }
        __syncthreads();
    }
#pragma unroll
    for (int i = 0; i < 4; i++) {
        int m = bm + ty * 4 + i, n = bn + tx * 2;
        if (m < M) {
            if (n < p.N)     p.C[(size_t)m * p.N + n]     = c[i][0];
            if (n + 1 < p.N) p.C[(size_t)m * p.N + n + 1] = c[i][1];
        }
    }
}

// =====================================================================
// Fused prep launch: z=0/1 encoders, z=2/3 weight precombine
// =====================================================================
__global__ __launch_bounds__(128, 4)
void prep_fused(EncArgs e0, EncArgs e1, PreArgs p0, PreArgs p1)
{
    extern __shared__ __align__(16) char smem[];
    int z = blockIdx.z;
    if (z == 0)      encoder_path(e0, smem);
    else if (z == 1) encoder_path(e1, smem);
    else if (z == 2) precombine_path(p0, smem);
    else             precombine_path(p1, smem);
}

// =====================================================================
// GEMM micro-kernel pieces shared by gemm1/gemm2:
// 64x64 tile, BK=16, 128 threads, per-thread 8m x 4n (f32x2 m-pairs).
// A in smem transposed [k][m] pitch 68; B in smem [k][n] pitch 68
// (NON-duplicated -> conflict-free LDS.128; dup via pk on ALU pipe).
// =====================================================================
#define GEMM_DECL()                                                     \
    __shared__ float As[16][68];                                        \
    __shared__ float Bs[16][68];                                        \
    const int tid = threadIdx.x;                                        \
    const int tx  = tid & 15;       /* 4n  */                           \
    const int ty  = tid >> 4;       /* 8m  */                           \
    const int a_k = (tid & 7) * 2;  /* 0..14 */                         \
    const int a_m = tid >> 3;       /* 0..15 */                         \
    const int b_n = tid & 63;                                           \
    const int b_k = tid >> 6;       /* 0..1 */                          \
    float2 pa[4]; float pb[8];                                          \
    ULL c[4][4];                                                        \
    _Pragma("unroll")                                                   \
    for (int i = 0; i < 4; i++)                                         \
        _Pragma("unroll")                                               \
        for (int j = 0; j < 4; j++) c[i][j] = 0ull;

#define GEMM_STORE_SMEM()                                               \
    _Pragma("unroll")                                                   \
    for (int i = 0; i < 4; i++) {                                       \
        int m = a_m + i * 16;                                           \
        As[a_k][m]     = pa[i].x;                                       \
        As[a_k + 1][m] = pa[i].y;                                       \
    }                                                                   \
    _Pragma("unroll")                                                   \
    for (int i = 0; i < 8; i++) Bs[b_k + i * 2][b_n] = pb[i];

#define GEMM_MMA()                                                      \
    _Pragma("unroll")                                                   \
    for (int kk = 0; kk < 16; kk++) {                                   \
        ulonglong2 a01 = *(const ulonglong2*)&As[kk][ty * 8];           \
        ulonglong2 a23 = *(const ulonglong2*)&As[kk][ty * 8 + 4];       \
        ULL a[4] = {a01.x, a01.y, a23.x, a23.y};                        \
        float4 bv = *(const float4*)&Bs[kk][tx * 4];                    \
        ULL b[4] = {pk(bv.x, bv.x), pk(bv.y, bv.y),                     \
                    pk(bv.z, bv.z), pk(bv.w, bv.w)};                    \
        _Pragma("unroll")                                               \
        for (int i = 0; i < 4; i++)                                     \
            _Pragma("unroll")                                           \
            for (int j = 0; j < 4; j++)                                 \
                fma2(c[i][j], a[i], b[j]);                              \
    }

#define GEMM_EPILOGUE(gg, bmv, bnv)                                     \
    _Pragma("unroll")                                                   \
    for (int j = 0; j < 4; j++) {                                       \
        int n = (bnv) + tx * 4 + j;                                     \
        if (n >= (gg).N) continue;                                      \
        float bv = (gg).bias[n];                                        \
        _Pragma("unroll")                                               \
        for (int i = 0; i < 4; i++) {                                   \
            float2 v = upk(c[i][j]);                                    \
            int m = (bmv) + ty * 8 + 2 * i;                             \
            (gg).C[(size_t)m * (gg).ldc + n]       = v.x + bv;          \
            (gg).C[(size_t)(m + 1) * (gg).ldc + n] = v.y + bv;          \
        }                                                               \
    }

// ---------------------------------------------------------------------
// GEMM1: H1 = U @ W1c + b1
// ---------------------------------------------------------------------
__global__ __launch_bounds__(128, 5)
void gemm1_fused(GemmArgs g0, GemmArgs g1)
{
    const GemmArgs g = blockIdx.z ? g1 : g0;
    const int bn = blockIdx.x * 64;
    if (bn >= g.N) return;
    const int bm = blockIdx.y * 64;

    GEMM_DECL();

    auto fetch = [&](int k0) {
        int kg = k0 + a_k;
#pragma unroll
        for (int i = 0; i < 4; i++) {
            int m = bm + a_m + i * 16;
            float2 v = make_float2(0.f, 0.f);
            if (kg + 1 < g.K)  v = *(const float2*)(g.A + (size_t)m * g.K + kg);
            else if (kg < g.K) v.x = g.A[(size_t)m * g.K + kg];
            pa[i] = v;
        }
#pragma unroll
        for (int i = 0; i < 8; i++) {
            int kgb = k0 + b_k + i * 2;
            int ng = bn + b_n;
            pb[i] = (kgb < g.K && ng < g.N) ? g.B[(size_t)kgb * g.N + ng] : 0.f;
        }
    };

    fetch(0);
    for (int k0 = 0; k0 < g.K; k0 += 16) {
        GEMM_STORE_SMEM();
        __syncthreads();
        if (k0 + 16 < g.K) fetch(k0 + 16);
        GEMM_MMA();
        __syncthreads();
    }
    GEMM_EPILOGUE(g, bm, bn);
}

// ---------------------------------------------------------------------
// GEMM2 with in-block LN stats + fused LN+ReLU on A:
// out = relu((H1 - mu)*rstd*gam + bet) @ W2 + b2
// ---------------------------------------------------------------------
__global__ __launch_bounds__(128, 5)
void gemm2_lnA(GemmArgs g0, GemmArgs g1,
               const float* __restrict__ gm0, const float* __restrict__ bt0,
               const float* __restrict__ gm1, const float* __restrict__ bt1)
{
    const GemmArgs g = blockIdx.z ? g1 : g0;
    const float* gam = blockIdx.z ? gm1 : gm0;
    const float* bet = blockIdx.z ? bt1 : bt0;
    const int bn = blockIdx.x * 64;
    if (bn >= g.N) return;
    const int bm = blockIdx.y * 64;

    __shared__ float muS[64], rsS[64];

    GEMM_DECL();

    // ---- prologue: row stats for this block's 64 rows (4 warps x 16 rows)
    {
        const int w = tid >> 5, lane = tid & 31;
        const float invN = 1.f / (float)g.K;
        for (int r = 0; r < 16; r++) {
            int row = w * 16 + r;
            const float* src = g.A + (size_t)(bm + row) * g.K;
            float s = 0.f, s2 = 0.f;
            for (int j = lane; j < g.K; j += 32) {
                float v = src[j];
                s += v; s2 = fmaf(v, v, s2);
            }
#pragma unroll
            for (int o = 16; o > 0; o >>= 1) {
                s  += __shfl_xor_sync(0xffffffffu, s, o);
                s2 += __shfl_xor_sync(0xffffffffu, s2, o);
            }
            if (lane == 0) {
                float mu = s * invN;
                float var = s2 * invN - mu * mu;
                muS[row] = mu;
                rsS[row] = rsqrtf(var + 1e-5f);
            }
        }
    }
    __syncthreads();

    auto fetch = [&](int k0) {
        int kg = k0 + a_k;
        bool ok0 = (kg < g.K), ok1 = (kg + 1 < g.K);
        float2 gk = make_float2(0.f, 0.f), bb = make_float2(0.f, 0.f);
        if (ok1)      { gk = *(const float2*)(gam + kg); bb = *(const float2*)(bet + kg); }
        else if (ok0) { gk.x = gam[kg]; bb.x = bet[kg]; }
#pragma unroll
        for (int i = 0; i < 4; i++) {
            int mloc = a_m + i * 16;
            int m = bm + mloc;
            float2 v = make_float2(0.f, 0.f);
            if (ok1)      v = *(const float2*)(g.A + (size_t)m * g.K + kg);
            else if (ok0) v.x = g.A[(size_t)m * g.K + kg];
            float mu = muS[mloc], rs = rsS[mloc];
            float2 r = make_float2(0.f, 0.f);
            if (ok0) r.x = fmaxf(0.f, (v.x - mu) * rs * gk.x + bb.x);
            if (ok1) r.y = fmaxf(0.f, (v.y - mu) * rs * gk.y + bb.y);
            pa[i] = r;
        }
#pragma unroll
        for (int i = 0; i < 8; i++) {
            int kgb = k0 + b_k + i * 2;
            int ng = bn + b_n;
            pb[i] = (kgb < g.K && ng < g.N) ? g.B[(size_t)kgb * g.N + ng] : 0.f;
        }
    };

    fetch(0);
    for (int k0 = 0; k0 < g.K; k0 += 16) {
        GEMM_STORE_SMEM();
        __syncthreads();
        if (k0 + 16 < g.K) fetch(k0 + 16);
        GEMM_MMA();
        __syncthreads();
    }
    GEMM_EPILOGUE(g, bm, bn);
}

// =====================================================================
// Host launcher
// =====================================================================
extern "C" void kernel_launch(void* const* d_in, const int* in_sizes, int n_in,
                              void* d_out, int out_size)
{
    const float* emb_P  = (const float*)d_in[0];
    const float* mask_P = (const float*)d_in[1];
    const float* emb_H  = (const float*)d_in[2];
    const float* mask_H = (const float*)d_in[3];
    const float* pep_Bc = (const float*)d_in[4];
    const float* pep_Ac = (const float*)d_in[5];
    const float* pep_Hc = (const float*)d_in[6];
    const float* pep_W1 = (const float*)d_in[7];
    const float* pep_b1 = (const float*)d_in[8];
    const float* pep_g  = (const float*)d_in[9];
    const float* pep_be = (const float*)d_in[10];
    const float* pep_W2 = (const float*)d_in[11];
    const float* pep_b2 = (const float*)d_in[12];
    const float* hla_Bc = (const float*)d_in[13];
    const float* hla_Ac = (const float*)d_in[14];
    const float* hla_Hc = (const float*)d_in[15];
    const float* hla_W1 = (const float*)d_in[16];
    const float* hla_b1 = (const float*)d_in[17];
    const float* hla_g  = (const float*)d_in[18];
    const float* hla_be = (const float*)d_in[19];
    const float* hla_W2 = (const float*)d_in[20];
    const float* hla_b2 = (const float*)d_in[21];
    float* out = (float*)d_out;

    float *UP, *UH, *W1cP, *W1cH, *H1P, *H1H;
    cudaGetSymbolAddress((void**)&UP,   g_UP);
    cudaGetSymbolAddress((void**)&UH,   g_UH);
    cudaGetSymbolAddress((void**)&W1cP, g_W1cP);
    cudaGetSymbolAddress((void**)&W1cH, g_W1cH);
    cudaGetSymbolAddress((void**)&H1P,  g_H1P);
    cudaGetSymbolAddress((void**)&H1H,  g_H1H);

    const int smemPrep = 384 * 64 + 4 * 384 * 4;   // 30720
    cudaFuncSetAttribute(prep_fused, cudaFuncAttributeMaxDynamicSharedMemorySize, smemPrep);

    // one launch: both encoders + both weight precombines
    {
        EncArgs eP { emb_P, mask_P, pep_Ac, pep_Bc, UP, 32 };
        EncArgs eH { emb_H, mask_H, hla_Ac, hla_Bc, UH, 384 };
        PreArgs pP { pep_Hc, pep_W1, W1cP, 358, 358, 12, 96 };
        PreArgs pH { hla_Hc, hla_W1, W1cH, 154, 154, 5, 40 };
        prep_fused<<<dim3(1024, 1, 4), 128, smemPrep>>>(eP, eH, pP, pH);
    }

    // GEMM1: H1 = U @ W1c + b1
    {
        GemmArgs gp { UP, W1cP, pep_b1, H1P, 358, 256, 358 };
        GemmArgs gh { UH, W1cH, hla_b1, H1H, 154, 256, 154 };
        gemm1_fused<<<dim3(6, 64, 2), 128>>>(gp, gh);
    }

    // GEMM2 (stats in-block) : out = relu(LN(H1)) @ W2 + b2
    {
        GemmArgs gp { H1P, pep_W2, pep_b2, out,       358, 358, 512 };
        GemmArgs gh { H1H, hla_W2, hla_b2, out + 358, 154, 154, 512 };
        gemm2_lnA<<<dim3(6, 64, 2), 128>>>(gp, gh,
                                           pep_g, pep_be, hla_g, hla_be);
    }
}